// round 5
// baseline (speedup 1.0000x reference)
#include <cuda_runtime.h>
#include <math.h>

#define BB 32
#define SS 512
#define HH 768
#define WE 150
#define LL 9
#define NPOS (BB*SS)            // 16384
#define NSPANS (BB*4096)        // 131072
#define T_STRIDE 304            // [0:150]=start part, [152:302]=end part
#define WD_STRIDE 152
#define RANKCAP 32
#define KEYS_PER_B (RANKCAP*RANKCAP*9)   // 9216
#define NKEYS (BB*KEYS_PER_B)            // 294912

// static scratch; zero-initialized at load; pipeline restores entry state each call.
__device__ float    g_T[NPOS*T_STRIDE];
__device__ float    g_WD[16*WD_STRIDE];
__device__ float    g_ULOG[(size_t)NSPANS*12];
__device__ int      g_used[NPOS];       // cleared by k_compact after read
__device__ int      g_list[NPOS];
__device__ int      g_slotOfPos[NPOS];
__device__ int      g_rank[NPOS];
__device__ int      g_bcount[BB];       // reset by k_scatter
__device__ int      g_count;            // reset by k_scatter
__device__ int      g_ckey[NKEYS];      // 0=empty, owner=i+1; cleared by k_scatter
__device__ int      g_uslot[NKEYS];
__device__ int      g_key[NSPANS];
__device__ int      g_spanslot[NSPANS];
__device__ unsigned g_uinfo[NSPANS];
__device__ int      g_ucount;           // reset by k_scatter

__device__ __forceinline__ int clampi(int v, int lo, int hi) { return min(max(v, lo), hi); }

__device__ __forceinline__ unsigned long long ffma2(unsigned long long a,
                                                    unsigned long long b,
                                                    unsigned long long c) {
    unsigned long long d;
    asm("fma.rn.f32x2 %0, %1, %2, %3;" : "=l"(d) : "l"(a), "l"(b), "l"(c));
    return d;
}
__device__ __forceinline__ unsigned long long pack2(float x) {
    unsigned long long d;
    asm("mov.b64 %0, {%1, %1};" : "=l"(d) : "f"(x));
    return d;
}

// K1: mark used positions + zero loss
__global__ void k_mark(const int* __restrict__ spans, float* __restrict__ loss_ptr) {
    int i = blockIdx.x * blockDim.x + threadIdx.x;
    if (i == 0) *loss_ptr = 0.f;
    if (i >= NSPANS) return;
    int b = i >> 12;
    int s = clampi(spans[3*i], 0, SS-1);
    int e = clampi(spans[3*i + 1], 0, SS-1);
    g_used[(b << 9) + s] = 1;
    g_used[(b << 9) + e] = 1;
}

// K2: compact used positions (and self-clear g_used)
__global__ void k_compact() {
    int i = blockIdx.x * blockDim.x + threadIdx.x;
    if (i >= NPOS) return;
    if (g_used[i]) {
        int slot = atomicAdd(&g_count, 1);
        g_list[slot] = i;
        g_slotOfPos[i] = slot;
        g_rank[i] = atomicAdd(&g_bcount[i >> 9], 1);
        g_used[i] = 0;
    }
}

// K3: claim (CAS winner owns + allocates unique slot)
__global__ void k_claim(const int* __restrict__ spans) {
    int i = blockIdx.x * blockDim.x + threadIdx.x;
    int b = i >> 12;
    int si = clampi(spans[3*i], 0, SS-1);
    int ei = clampi(spans[3*i + 1], 0, SS-1);
    int wi = clampi(spans[3*i + 2], 0, 8);
    int rs = g_rank[(b << 9) + si];
    int re = g_rank[(b << 9) + ei];
    int key = -2;
    bool own;
    if (rs < RANKCAP && re < RANKCAP) {
        key = b * KEYS_PER_B + (rs * RANKCAP + re) * 9 + wi;
        own = (atomicCAS(&g_ckey[key], 0, i + 1) == 0);
    } else {
        own = true;
    }
    g_key[i] = key;
    if (own) {
        int ss = g_slotOfPos[(b << 9) + si];
        int se = g_slotOfPos[(b << 9) + ei];
        int slot = atomicAdd(&g_ucount, 1);
        g_uinfo[slot] = (unsigned)ss | ((unsigned)se << 14) | ((unsigned)wi << 28);
        if (key >= 0) g_uslot[key] = slot;
        else g_spanslot[i] = slot;
    }
}

// K4: T projection. task < ngemm: 2 rows x 300 cols x k=768, in-block split-K x2,
// direct writes (no atomics, no pre-zero). tasks >= ngemm: WD rows (4-way k-split).
__global__ void __launch_bounds__(600)
k_TgemmWD(const float* __restrict__ seq, const float* __restrict__ W1,
          const float* __restrict__ wt, const float* __restrict__ b1) {
    __shared__ float sA[2 * HH];     // 2 relu'd seq rows (or relu'd wt row)
    __shared__ float sRed[600];
    int cnt = g_count;
    int ngemm = (cnt + 1) >> 1;
    int ntasks = ngemm + 9;
    int tid = threadIdx.x;
    int ks = tid / 300;          // 0..1 (k-group) for gemm tasks
    int jj = tid - ks * 300;     // 0..299 column
    const float* wp = (jj < 150) ? (W1 + jj) : (W1 + HH * WE + (jj - 150));
    int col = (jj < 150) ? jj : (152 + jj - 150);

    for (int task = blockIdx.x; task < ntasks; task += gridDim.x) {
        if (task < ngemm) {
            int r0 = task * 2;
            int r1 = min(r0 + 1, cnt - 1);
            const float* s0 = seq + (size_t)g_list[r0] * HH;
            const float* s1 = seq + (size_t)g_list[r1] * HH;
            for (int t = tid; t < HH; t += 600) {
                sA[t]      = fmaxf(s0[t], 0.f);
                sA[HH + t] = fmaxf(s1[t], 0.f);
            }
            __syncthreads();
            {
                float a0 = 0.f, a1 = 0.f;
                int k0 = ks * 384;
                const float* w = wp + (size_t)k0 * WE;
                #pragma unroll 8
                for (int k = 0; k < 384; k++) {
                    float wv = w[(size_t)k * WE];
                    a0 = fmaf(sA[k0 + k], wv, a0);
                    a1 = fmaf(sA[HH + k0 + k], wv, a1);
                }
                if (ks == 1) { sRed[jj] = a0; sRed[300 + jj] = a1; }
                __syncthreads();
                if (ks == 0) {
                    a0 += sRed[jj];
                    a1 += sRed[300 + jj];
                    g_T[(size_t)r0 * T_STRIDE + col] = a0;
                    if (r0 + 1 < cnt)
                        g_T[(size_t)(r0 + 1) * T_STRIDE + col] = a1;
                }
            }
            __syncthreads();
        } else {
            int w = task - ngemm;   // 0..8
            for (int t = tid; t < 150; t += 600) sA[t] = fmaxf(wt[w*150 + t], 0.f);
            __syncthreads();
            int g = tid / 150;       // 0..3
            int j = tid - g * 150;
            if (tid < 600) {
                int kst = g * 38;
                int ken = min(150, kst + 38);
                float acc = (g == 0) ? b1[j] : 0.f;
                for (int k = kst; k < ken; k++)
                    acc = fmaf(sA[k], W1[(size_t)(2*HH + k) * WE + j], acc);
                if (g > 0) sRed[(g-1)*150 + j] = acc;
                __syncthreads();
                if (g == 0)
                    g_WD[w * WD_STRIDE + j] = acc + sRed[j] + sRed[150 + j] + sRed[300 + j];
            }
            __syncthreads();
        }
    }
}

// K5: unique rows -> h1 -> @W2+b2 (FFMA2) -> @W3+b3 -> g_ULOG
#define UT 64
__global__ void __launch_bounds__(256, 1)
k_uniq(const float* __restrict__ W2, const float* __restrict__ b2,
       const float* __restrict__ W3, const float* __restrict__ b3)
{
    extern __shared__ float sm[];
    float* sW2 = sm;                     // [150][160]
    float* sU  = sm + 24000;             // union: h1T [152][64] / h2 [64][164]
    float* sW3 = sm + 34496;             // [150][12]
    float* sB2 = sm + 36296;             // [160]
    float* sB3 = sm + 36456;             // [12]
    unsigned* sInfo = (unsigned*)(sm + 36468);  // [64]
    int tid = threadIdx.x;

    for (int idx = tid; idx < 150*160; idx += 256) {
        int k = idx / 160, j = idx - k*160;
        sW2[idx] = (j < 150) ? W2[k*150 + j] : 0.f;
    }
    for (int idx = tid; idx < 150*12; idx += 256) {
        int k = idx / 12, l = idx - k*12;
        sW3[idx] = (l < 9) ? W3[k*9 + l] : 0.f;
    }
    if (tid < 160) sB2[tid] = (tid < 150) ? b2[tid] : 0.f;
    if (tid < 12)  sB3[tid] = (tid < 9)  ? b3[tid] : 0.f;

    int nu = g_ucount;
    int r0 = (tid & 15) * 4;     // 4 consecutive rows
    int c0 = (tid >> 4) * 10;    // 10 cols = 5 packed pairs

    for (int base = blockIdx.x * UT; base < nu; base += gridDim.x * UT) {
        if (tid < UT)
            sInfo[tid] = (base + tid < nu) ? g_uinfo[base + tid] : 0u;
        __syncthreads();

        // gather h1, k-major [k][64], float4 over k
        for (int idx = tid; idx < 38*64; idx += 256) {
            int kq = idx >> 6, r = idx & 63;
            unsigned info = sInfo[r];
            int ss = info & 0x3FFF, se = (info >> 14) & 0x3FFF, w = info >> 28;
            float4 ts = *(const float4*)&g_T[(size_t)ss*T_STRIDE + kq*4];
            float4 te = *(const float4*)&g_T[(size_t)se*T_STRIDE + 152 + kq*4];
            float4 wd = *(const float4*)&g_WD[w*WD_STRIDE + kq*4];
            sU[(kq*4 + 0)*64 + r] = fmaxf(ts.x + te.x + wd.x, 0.f);
            sU[(kq*4 + 1)*64 + r] = fmaxf(ts.y + te.y + wd.y, 0.f);
            sU[(kq*4 + 2)*64 + r] = fmaxf(ts.z + te.z + wd.z, 0.f);
            sU[(kq*4 + 3)*64 + r] = fmaxf(ts.w + te.w + wd.w, 0.f);
        }
        __syncthreads();

        // h2 = h1 @ W2 + b2, packed column pairs (FFMA2)
        unsigned long long acc[4][5];
        {
            const unsigned long long* bp = (const unsigned long long*)&sB2[c0];
            #pragma unroll
            for (int p = 0; p < 5; p++) {
                unsigned long long bv = bp[p];
                #pragma unroll
                for (int ri = 0; ri < 4; ri++) acc[ri][p] = bv;
            }
        }
        #pragma unroll 2
        for (int k = 0; k < 150; k++) {
            float4 a = *(const float4*)&sU[k*64 + r0];
            unsigned long long ap[4] = {pack2(a.x), pack2(a.y), pack2(a.z), pack2(a.w)};
            const unsigned long long* bw = (const unsigned long long*)&sW2[k*160 + c0];
            unsigned long long bv[5] = {bw[0], bw[1], bw[2], bw[3], bw[4]};
            #pragma unroll
            for (int ri = 0; ri < 4; ri++)
                #pragma unroll
                for (int p = 0; p < 5; p++)
                    acc[ri][p] = ffma2(ap[ri], bv[p], acc[ri][p]);
        }
        __syncthreads();   // all h1 reads done before overwriting sU

        #pragma unroll
        for (int ri = 0; ri < 4; ri++)
            #pragma unroll
            for (int p = 0; p < 5; p++)
                *(unsigned long long*)&sU[(r0 + ri)*164 + c0 + 2*p] = acc[ri][p];
        __syncthreads();

        // logits = h2 @ W3 + b3
        for (int idx = tid; idx < UT*LL; idx += 256) {
            int r = idx / LL, l = idx - r*LL;
            float a = sB3[l];
            #pragma unroll 5
            for (int k = 0; k < 150; k++)
                a = fmaf(sU[r*164 + k], sW3[k*12 + l], a);
            if (base + r < nu)
                g_ULOG[(size_t)(base + r)*12 + l] = a;
        }
        __syncthreads();
    }
}

// K6: scatter logits per span + NLL loss + restore global state invariants
__global__ void k_scatter(const int* __restrict__ mask,
                          const int* __restrict__ label,
                          float* __restrict__ out)
{
    __shared__ float sL;
    if (threadIdx.x == 0) sL = 0.f;
    __syncthreads();
    int i = blockIdx.x * blockDim.x + threadIdx.x;
    float contrib = 0.f;
    if (i < NSPANS) {
        int key = g_key[i];
        int slot;
        if (key >= 0) { slot = g_uslot[key]; g_ckey[key] = 0; }
        else          { slot = g_spanslot[i]; }
        const float* Lr = &g_ULOG[(size_t)slot * 12];
        float4 p0 = *(const float4*)Lr;
        float4 p1 = *(const float4*)(Lr + 4);
        float l8 = Lr[8];
        float L[9] = {p0.x, p0.y, p0.z, p0.w, p1.x, p1.y, p1.z, p1.w, l8};
        float* o = out + (size_t)i * LL;
        #pragma unroll
        for (int l = 0; l < LL; l++) o[l] = L[l];
        if (mask[i] == 1) {
            float m = L[0];
            #pragma unroll
            for (int l = 1; l < LL; l++) m = fmaxf(m, L[l]);
            float ssum = 0.f;
            #pragma unroll
            for (int l = 0; l < LL; l++) ssum += expf(L[l] - m);
            int lb = clampi(label[i], 0, LL-1);
            contrib = (m + logf(ssum)) - L[lb];
        }
    }
    atomicAdd(&sL, contrib);
    __syncthreads();
    if (threadIdx.x == 0 && sL != 0.f)
        atomicAdd(&out[(size_t)NSPANS * LL], sL);
    if (blockIdx.x == 0 && threadIdx.x == 0) {
        g_count = 0; g_ucount = 0;
        #pragma unroll
        for (int w = 0; w < BB; w++) g_bcount[w] = 0;
    }
}

extern "C" void kernel_launch(void* const* d_in, const int* in_sizes, int n_in,
                              void* d_out, int out_size) {
    const float* seq = (const float*)d_in[0];
    const float* wt  = (const float*)d_in[1];
    const float* W1  = (const float*)d_in[2];
    const float* b1  = (const float*)d_in[3];
    const float* W2  = (const float*)d_in[4];
    const float* b2  = (const float*)d_in[5];
    const float* W3  = (const float*)d_in[6];
    const float* b3  = (const float*)d_in[7];
    const int* spans = (const int*)d_in[8];
    const int* smask = (const int*)d_in[9];
    const int* slab  = (const int*)d_in[10];
    float* out = (float*)d_out;

    static const size_t SMEM_UNIQ = (size_t)(36468 + 64) * 4;   // 146128 B
    cudaFuncSetAttribute(k_uniq, cudaFuncAttributeMaxDynamicSharedMemorySize, (int)SMEM_UNIQ);

    k_mark<<<NSPANS/256, 256>>>(spans, out + (size_t)NSPANS * LL);
    k_compact<<<NPOS/256, 256>>>();
    k_claim<<<NSPANS/256, 256>>>(spans);
    k_TgemmWD<<<160, 600>>>(seq, W1, wt, b1);
    k_uniq<<<148, 256, SMEM_UNIQ>>>(W2, b2, W3, b3);
    k_scatter<<<NSPANS/256, 256>>>(smask, slab, out);
}

// round 8
// speedup vs baseline: 1.0327x; 1.0327x over previous
#include <cuda_runtime.h>
#include <math.h>

#define BB 32
#define SS 512
#define HH 768
#define WE 150
#define LL 9
#define NPOS (BB*SS)            // 16384
#define NSPANS (BB*4096)        // 131072
#define T_STRIDE 304            // [0:150]=start part, [152:302]=end part
#define WD_STRIDE 152
#define RANKCAP 32
#define KEYS_PER_B (RANKCAP*RANKCAP*9)   // 9216
#define NKEYS (BB*KEYS_PER_B)            // 294912
#define TROWS 16

typedef unsigned long long ull;

// static scratch; zero-initialized at load; pipeline restores entry state each call.
__device__ float    g_T[NPOS*T_STRIDE];
__device__ float    g_WD[16*WD_STRIDE];
__device__ float    g_ULOG[(size_t)NSPANS*12];
__device__ int      g_used[NPOS];       // cleared by k_compact after read
__device__ int      g_list[NPOS];
__device__ int      g_slotOfPos[NPOS];
__device__ int      g_rank[NPOS];
__device__ int      g_bcount[BB];       // reset by k_scatter
__device__ int      g_count;            // reset by k_scatter
__device__ int      g_ckey[NKEYS];      // 0=empty, owner=i+1; cleared by k_scatter
__device__ int      g_uslot[NKEYS];
__device__ int      g_key[NSPANS];
__device__ int      g_spanslot[NSPANS];
__device__ unsigned g_uinfo[NSPANS];
__device__ int      g_ucount;           // reset by k_scatter
__device__ int      g_tile;             // uniq work-steal counter; reset by k_scatter

__device__ __forceinline__ int clampi(int v, int lo, int hi) { return min(max(v, lo), hi); }

__device__ __forceinline__ ull ffma2(ull a, ull b, ull c) {
    ull d;
    asm("fma.rn.f32x2 %0, %1, %2, %3;" : "=l"(d) : "l"(a), "l"(b), "l"(c));
    return d;
}
__device__ __forceinline__ ull pack2(float x) {
    ull d;
    asm("mov.b64 %0, {%1, %1};" : "=l"(d) : "f"(x));
    return d;
}
__device__ __forceinline__ void unpack2(ull v, float& lo, float& hi) {
    asm("mov.b64 {%0, %1}, %2;" : "=f"(lo), "=f"(hi) : "l"(v));
}

// K1: mark used positions + zero loss
__global__ void k_mark(const int* __restrict__ spans, float* __restrict__ loss_ptr) {
    int i = blockIdx.x * blockDim.x + threadIdx.x;
    if (i == 0) *loss_ptr = 0.f;
    if (i >= NSPANS) return;
    int b = i >> 12;
    int s = clampi(spans[3*i], 0, SS-1);
    int e = clampi(spans[3*i + 1], 0, SS-1);
    g_used[(b << 9) + s] = 1;
    g_used[(b << 9) + e] = 1;
}

// K2: compact used positions (and self-clear g_used)
__global__ void k_compact() {
    int i = blockIdx.x * blockDim.x + threadIdx.x;
    if (i >= NPOS) return;
    if (g_used[i]) {
        int slot = atomicAdd(&g_count, 1);
        g_list[slot] = i;
        g_slotOfPos[i] = slot;
        g_rank[i] = atomicAdd(&g_bcount[i >> 9], 1);
        g_used[i] = 0;
    }
}

// K3: blocks [0,512): claim (CAS winner owns + allocates unique slot)
//     blocks [512,544): zero g_T rows for all used slots (pre-atomics)
__global__ void k_claim(const int* __restrict__ spans) {
    int bi = blockIdx.x;
    int tid = threadIdx.x;
    if (bi < 512) {
        int i = bi * 256 + tid;
        int b = i >> 12;
        int si = clampi(spans[3*i], 0, SS-1);
        int ei = clampi(spans[3*i + 1], 0, SS-1);
        int wi = clampi(spans[3*i + 2], 0, 8);
        int rs = g_rank[(b << 9) + si];
        int re = g_rank[(b << 9) + ei];
        int key = -2;
        bool own;
        if (rs < RANKCAP && re < RANKCAP) {
            key = b * KEYS_PER_B + (rs * RANKCAP + re) * 9 + wi;
            own = (atomicCAS(&g_ckey[key], 0, i + 1) == 0);
        } else {
            own = true;
        }
        g_key[i] = key;
        if (own) {
            int ss = g_slotOfPos[(b << 9) + si];
            int se = g_slotOfPos[(b << 9) + ei];
            int slot = atomicAdd(&g_ucount, 1);
            g_uinfo[slot] = (unsigned)ss | ((unsigned)se << 14) | ((unsigned)wi << 28);
            if (key >= 0) g_uslot[key] = slot;
            else g_spanslot[i] = slot;
        }
    } else {
        int cnt = g_count;
        for (int slot = bi - 512; slot < cnt; slot += 32) {
            float4* tz = (float4*)(g_T + (size_t)slot * T_STRIDE);
            for (int t = tid; t < T_STRIDE/4; t += 256)
                tz[t] = make_float4(0.f, 0.f, 0.f, 0.f);
        }
    }
}

// K4: T projection. Tasks: (rowtile of 16) x (ksplit of 4, k=192 each).
// Per thread: colpair cp (0..149), rowgroup rg (0..1) -> 8 rows x 2 cols in FFMA2.
// Partial sums combined via atomicAdd into pre-zeroed g_T.
// Tasks >= ngemm: WD rows.
__global__ void __launch_bounds__(300)
k_TgemmWD(const float* __restrict__ seq, const float* __restrict__ W1,
          const float* __restrict__ wt, const float* __restrict__ b1) {
    __shared__ float sA[192 * TROWS];    // staged relu'd rows, [k][16]
    __shared__ float sRed[160];
    int cnt = g_count;
    int nrt = (cnt + TROWS - 1) / TROWS;
    int ngemm = nrt * 4;
    int ntasks = ngemm + 9;
    int tid = threadIdx.x;
    int cp = tid % 150;
    int rg = tid / 150;          // 0 or 1
    int jj = 2 * cp;
    const float* wbase = (jj < 150) ? (W1 + jj) : (W1 + (size_t)HH * WE + (jj - 150));
    int col0 = (jj < 150) ? jj : (jj + 2);   // 152 + (jj-150)

    for (int task = blockIdx.x; task < ntasks; task += gridDim.x) {
        if (task < ngemm) {
            int rt = task >> 2, ks = task & 3;
            int r0 = rt * TROWS, k0 = ks * 192;
            for (int idx = tid; idx < 192 * TROWS; idx += 300) {
                int r = idx / 192, k = idx - r * 192;
                int row = r0 + r;
                float v = 0.f;
                if (row < cnt)
                    v = fmaxf(seq[(size_t)g_list[row] * HH + k0 + k], 0.f);
                sA[k * TROWS + r] = v;
            }
            __syncthreads();

            ull acc[4][2];
            #pragma unroll
            for (int p = 0; p < 4; p++) { acc[p][0] = 0ull; acc[p][1] = 0ull; }

            const float* wp = wbase + (size_t)k0 * WE;
            #pragma unroll 4
            for (int k = 0; k < 192; k++) {
                float2 w2 = *(const float2*)&wp[(size_t)k * WE];
                ull b0 = pack2(w2.x), b1v = pack2(w2.y);
                const float* ab = &sA[k * TROWS + rg * 8];
                #pragma unroll
                for (int p = 0; p < 4; p++) {
                    ull a = *(const ull*)&ab[2 * p];
                    acc[p][0] = ffma2(a, b0, acc[p][0]);
                    acc[p][1] = ffma2(a, b1v, acc[p][1]);
                }
            }

            int rbase = r0 + rg * 8;
            #pragma unroll
            for (int p = 0; p < 4; p++) {
                #pragma unroll
                for (int c = 0; c < 2; c++) {
                    float lo, hi;
                    unpack2(acc[p][c], lo, hi);
                    int rA = rbase + 2 * p;
                    if (rA < cnt)
                        atomicAdd(&g_T[(size_t)rA * T_STRIDE + col0 + c], lo);
                    if (rA + 1 < cnt)
                        atomicAdd(&g_T[(size_t)(rA + 1) * T_STRIDE + col0 + c], hi);
                }
            }
            __syncthreads();
        } else {
            int w = task - ngemm;   // 0..8
            for (int t = tid; t < 150; t += 300) sA[t] = fmaxf(wt[w*150 + t], 0.f);
            __syncthreads();
            int g = tid / 150;      // 0..1
            int j = tid - g * 150;
            float acc = (g == 0) ? b1[j] : 0.f;
            int kst = g * 75;
            for (int k = kst; k < kst + 75; k++)
                acc = fmaf(sA[k], W1[(size_t)(2*HH + k) * WE + j], acc);
            if (g == 1) sRed[j] = acc;
            __syncthreads();
            if (g == 0) g_WD[w * WD_STRIDE + j] = acc + sRed[j];
            __syncthreads();
        }
    }
}

// K5: unique rows -> h1 -> @W2+b2 (FFMA2) -> @W3+b3 -> g_ULOG. Work-stealing tiles.
#define UT 64
__global__ void __launch_bounds__(256, 1)
k_uniq(const float* __restrict__ W2, const float* __restrict__ b2,
       const float* __restrict__ W3, const float* __restrict__ b3)
{
    extern __shared__ float sm[];
    float* sW2 = sm;                     // [150][160]
    float* sU  = sm + 24000;             // union: h1T [152][64] / h2 [64][164]
    float* sW3 = sm + 34496;             // [150][12]
    float* sB2 = sm + 36296;             // [160]
    float* sB3 = sm + 36456;             // [12]
    unsigned* sInfo = (unsigned*)(sm + 36468);  // [64]
    int* sTile = (int*)(sm + 36468 + 64);
    int tid = threadIdx.x;

    for (int idx = tid; idx < 150*160; idx += 256) {
        int k = idx / 160, j = idx - k*160;
        sW2[idx] = (j < 150) ? W2[k*150 + j] : 0.f;
    }
    for (int idx = tid; idx < 150*12; idx += 256) {
        int k = idx / 12, l = idx - k*12;
        sW3[idx] = (l < 9) ? W3[k*9 + l] : 0.f;
    }
    if (tid < 160) sB2[tid] = (tid < 150) ? b2[tid] : 0.f;
    if (tid < 12)  sB3[tid] = (tid < 9)  ? b3[tid] : 0.f;

    int nu = g_ucount;
    int r0 = (tid & 15) * 4;     // 4 consecutive rows
    int c0 = (tid >> 4) * 10;    // 10 cols = 5 packed pairs

    for (;;) {
        if (tid == 0) *sTile = atomicAdd(&g_tile, 1);
        __syncthreads();
        int base = (*sTile) * UT;
        if (base >= nu) break;

        if (tid < UT)
            sInfo[tid] = (base + tid < nu) ? g_uinfo[base + tid] : 0u;
        __syncthreads();

        // gather h1, k-major [k][64], float4 over k
        for (int idx = tid; idx < 38*64; idx += 256) {
            int kq = idx >> 6, r = idx & 63;
            unsigned info = sInfo[r];
            int ss = info & 0x3FFF, se = (info >> 14) & 0x3FFF, w = info >> 28;
            float4 ts = *(const float4*)&g_T[(size_t)ss*T_STRIDE + kq*4];
            float4 te = *(const float4*)&g_T[(size_t)se*T_STRIDE + 152 + kq*4];
            float4 wd = *(const float4*)&g_WD[w*WD_STRIDE + kq*4];
            sU[(kq*4 + 0)*64 + r] = fmaxf(ts.x + te.x + wd.x, 0.f);
            sU[(kq*4 + 1)*64 + r] = fmaxf(ts.y + te.y + wd.y, 0.f);
            sU[(kq*4 + 2)*64 + r] = fmaxf(ts.z + te.z + wd.z, 0.f);
            sU[(kq*4 + 3)*64 + r] = fmaxf(ts.w + te.w + wd.w, 0.f);
        }
        __syncthreads();

        // h2 = h1 @ W2 + b2, packed column pairs (FFMA2)
        ull acc[4][5];
        {
            const ull* bp = (const ull*)&sB2[c0];
            #pragma unroll
            for (int p = 0; p < 5; p++) {
                ull bv = bp[p];
                #pragma unroll
                for (int ri = 0; ri < 4; ri++) acc[ri][p] = bv;
            }
        }
        #pragma unroll 2
        for (int k = 0; k < 150; k++) {
            float4 a = *(const float4*)&sU[k*64 + r0];
            ull ap[4] = {pack2(a.x), pack2(a.y), pack2(a.z), pack2(a.w)};
            const ull* bw = (const ull*)&sW2[k*160 + c0];
            ull bv[5] = {bw[0], bw[1], bw[2], bw[3], bw[4]};
            #pragma unroll
            for (int ri = 0; ri < 4; ri++)
                #pragma unroll
                for (int p = 0; p < 5; p++)
                    acc[ri][p] = ffma2(ap[ri], bv[p], acc[ri][p]);
        }
        __syncthreads();   // all h1 reads done before overwriting sU

        #pragma unroll
        for (int ri = 0; ri < 4; ri++)
            #pragma unroll
            for (int p = 0; p < 5; p++)
                *(ull*)&sU[(r0 + ri)*164 + c0 + 2*p] = acc[ri][p];
        __syncthreads();

        // logits = h2 @ W3 + b3
        for (int idx = tid; idx < UT*LL; idx += 256) {
            int r = idx / LL, l = idx - r*LL;
            float a = sB3[l];
            #pragma unroll 5
            for (int k = 0; k < 150; k++)
                a = fmaf(sU[r*164 + k], sW3[k*12 + l], a);
            if (base + r < nu)
                g_ULOG[(size_t)(base + r)*12 + l] = a;
        }
        __syncthreads();
    }
}

// K6: scatter logits per span + NLL loss + restore global state invariants
__global__ void k_scatter(const int* __restrict__ mask,
                          const int* __restrict__ label,
                          float* __restrict__ out)
{
    __shared__ float sL;
    if (threadIdx.x == 0) sL = 0.f;
    __syncthreads();
    int i = blockIdx.x * blockDim.x + threadIdx.x;
    float contrib = 0.f;
    if (i < NSPANS) {
        int key = g_key[i];
        int slot;
        if (key >= 0) { slot = g_uslot[key]; g_ckey[key] = 0; }
        else          { slot = g_spanslot[i]; }
        const float* Lr = &g_ULOG[(size_t)slot * 12];
        float4 p0 = *(const float4*)Lr;
        float4 p1 = *(const float4*)(Lr + 4);
        float l8 = Lr[8];
        float L[9] = {p0.x, p0.y, p0.z, p0.w, p1.x, p1.y, p1.z, p1.w, l8};
        float* o = out + (size_t)i * LL;
        #pragma unroll
        for (int l = 0; l < LL; l++) o[l] = L[l];
        if (mask[i] == 1) {
            float m = L[0];
            #pragma unroll
            for (int l = 1; l < LL; l++) m = fmaxf(m, L[l]);
            float ssum = 0.f;
            #pragma unroll
            for (int l = 0; l < LL; l++) ssum += expf(L[l] - m);
            int lb = clampi(label[i], 0, LL-1);
            contrib = (m + logf(ssum)) - L[lb];
        }
    }
    atomicAdd(&sL, contrib);
    __syncthreads();
    if (threadIdx.x == 0 && sL != 0.f)
        atomicAdd(&out[(size_t)NSPANS * LL], sL);
    if (blockIdx.x == 0 && threadIdx.x == 0) {
        g_count = 0; g_ucount = 0; g_tile = 0;
        #pragma unroll
        for (int w = 0; w < BB; w++) g_bcount[w] = 0;
    }
}

extern "C" void kernel_launch(void* const* d_in, const int* in_sizes, int n_in,
                              void* d_out, int out_size) {
    const float* seq = (const float*)d_in[0];
    const float* wt  = (const float*)d_in[1];
    const float* W1  = (const float*)d_in[2];
    const float* b1  = (const float*)d_in[3];
    const float* W2  = (const float*)d_in[4];
    const float* b2  = (const float*)d_in[5];
    const float* W3  = (const float*)d_in[6];
    const float* b3  = (const float*)d_in[7];
    const int* spans = (const int*)d_in[8];
    const int* smask = (const int*)d_in[9];
    const int* slab  = (const int*)d_in[10];
    float* out = (float*)d_out;

    static const size_t SMEM_UNIQ = (size_t)(36468 + 64 + 4) * 4;
    cudaFuncSetAttribute(k_uniq, cudaFuncAttributeMaxDynamicSharedMemorySize, (int)SMEM_UNIQ);

    k_mark<<<NSPANS/256, 256>>>(spans, out + (size_t)NSPANS * LL);
    k_compact<<<NPOS/256, 256>>>();
    k_claim<<<544, 256>>>(spans);
    k_TgemmWD<<<148, 300>>>(seq, W1, wt, b1);
    k_uniq<<<148, 256, SMEM_UNIQ>>>(W2, b2, W3, b3);
    k_scatter<<<NSPANS/256, 256>>>(smask, slab, out);
}

// round 9
// speedup vs baseline: 1.0634x; 1.0297x over previous
#include <cuda_runtime.h>
#include <math.h>

#define BB 32
#define SS 512
#define HH 768
#define WE 150
#define LL 9
#define NPOS (BB*SS)            // 16384
#define NSPANS (BB*4096)        // 131072
#define T_STRIDE 304            // [0:150]=start part, [152:302]=end part
#define WD_STRIDE 152
#define RANKCAP 32
#define KEYS_PER_B (RANKCAP*RANKCAP*9)   // 9216
#define NKEYS (BB*KEYS_PER_B)            // 294912
#define TROWS 8
#define KCH 24

typedef unsigned long long ull;

// static scratch; zero-initialized at load; pipeline restores entry state each call.
__device__ float    g_T[NPOS*T_STRIDE];
__device__ float    g_WD[16*WD_STRIDE];
__device__ float    g_ULOG[(size_t)NSPANS*12];
__device__ int      g_used[NPOS];       // cleared by k_compact after read
__device__ int      g_list[NPOS];
__device__ int      g_slotOfPos[NPOS];
__device__ int      g_rank[NPOS];
__device__ int      g_bcount[BB];       // reset by k_scatter
__device__ int      g_count;            // reset by k_scatter
__device__ int      g_ckey[NKEYS];      // 0=empty, owner=i+1; cleared by k_scatter
__device__ int      g_uslot[NKEYS];
__device__ int      g_key[NSPANS];
__device__ int      g_spanslot[NSPANS];
__device__ unsigned g_uinfo[NSPANS];
__device__ int      g_ucount;           // reset by k_scatter
__device__ int      g_tile;             // uniq work-steal counter; reset by k_scatter

__device__ __forceinline__ int clampi(int v, int lo, int hi) { return min(max(v, lo), hi); }

__device__ __forceinline__ ull ffma2(ull a, ull b, ull c) {
    ull d;
    asm("fma.rn.f32x2 %0, %1, %2, %3;" : "=l"(d) : "l"(a), "l"(b), "l"(c));
    return d;
}
__device__ __forceinline__ ull pack2(float x) {
    ull d;
    asm("mov.b64 %0, {%1, %1};" : "=l"(d) : "f"(x));
    return d;
}
__device__ __forceinline__ void unpack2(ull v, float& lo, float& hi) {
    asm("mov.b64 {%0, %1}, %2;" : "=f"(lo), "=f"(hi) : "l"(v));
}

// K1: mark used positions + zero loss
__global__ void k_mark(const int* __restrict__ spans, float* __restrict__ loss_ptr) {
    int i = blockIdx.x * blockDim.x + threadIdx.x;
    if (i == 0) *loss_ptr = 0.f;
    if (i >= NSPANS) return;
    int b = i >> 12;
    int s = clampi(spans[3*i], 0, SS-1);
    int e = clampi(spans[3*i + 1], 0, SS-1);
    g_used[(b << 9) + s] = 1;
    g_used[(b << 9) + e] = 1;
}

// K2: compact used positions (and self-clear g_used)
__global__ void k_compact() {
    int i = blockIdx.x * blockDim.x + threadIdx.x;
    if (i >= NPOS) return;
    if (g_used[i]) {
        int slot = atomicAdd(&g_count, 1);
        g_list[slot] = i;
        g_slotOfPos[i] = slot;
        g_rank[i] = atomicAdd(&g_bcount[i >> 9], 1);
        g_used[i] = 0;
    }
}

// K3: blocks [0,512): claim (CAS winner owns + allocates unique slot)
//     blocks [512,544): zero g_T rows for all used slots (pre-atomics)
__global__ void k_claim(const int* __restrict__ spans) {
    int bi = blockIdx.x;
    int tid = threadIdx.x;
    if (bi < 512) {
        int i = bi * 256 + tid;
        int b = i >> 12;
        int si = clampi(spans[3*i], 0, SS-1);
        int ei = clampi(spans[3*i + 1], 0, SS-1);
        int wi = clampi(spans[3*i + 2], 0, 8);
        int rs = g_rank[(b << 9) + si];
        int re = g_rank[(b << 9) + ei];
        int key = -2;
        bool own;
        if (rs < RANKCAP && re < RANKCAP) {
            key = b * KEYS_PER_B + (rs * RANKCAP + re) * 9 + wi;
            own = (atomicCAS(&g_ckey[key], 0, i + 1) == 0);
        } else {
            own = true;
        }
        g_key[i] = key;
        if (own) {
            int ss = g_slotOfPos[(b << 9) + si];
            int se = g_slotOfPos[(b << 9) + ei];
            int slot = atomicAdd(&g_ucount, 1);
            g_uinfo[slot] = (unsigned)ss | ((unsigned)se << 14) | ((unsigned)wi << 28);
            if (key >= 0) g_uslot[key] = slot;
            else g_spanslot[i] = slot;
        }
    } else {
        int cnt = g_count;
        for (int slot = bi - 512; slot < cnt; slot += 32) {
            float4* tz = (float4*)(g_T + (size_t)slot * T_STRIDE);
            for (int t = tid; t < T_STRIDE/4; t += 256)
                tz[t] = make_float4(0.f, 0.f, 0.f, 0.f);
        }
    }
}

// stage one 24-k chunk of [W1a|W1b] columns into smem [kk][300(+pad 304)]
__device__ __forceinline__ void stageW(float* __restrict__ dst,
                                       const float* __restrict__ W1, int kbase) {
    int tid = threadIdx.x;
    const float* src = (tid < 150)
        ? (W1 + (size_t)kbase * WE + tid)
        : (W1 + (size_t)(HH + kbase) * WE + (tid - 150));
    #pragma unroll
    for (int kk = 0; kk < KCH; kk++)
        dst[kk * 304 + tid] = src[(size_t)kk * WE];
}

// K4: T projection. Tasks: (rowtile of 8) x (ksplit of 4, k=192).
// W1 double-buffered through smem; FFMA2 compute; atomicAdd combine into
// pre-zeroed g_T. Tasks >= ngemm: WD rows.
__global__ void __launch_bounds__(300)
k_TgemmWD(const float* __restrict__ seq, const float* __restrict__ W1,
          const float* __restrict__ wt, const float* __restrict__ b1) {
    extern __shared__ float smem[];
    float* sW  = smem;                      // [2][KCH][304]
    float* sA  = smem + 2*KCH*304;          // [192][8] k-major
    int*  sRow = (int*)(sA + 192*TROWS);    // [8]
    float* sRed = (float*)(sRow + 8);       // [160]

    int cnt = g_count;
    int nrt = (cnt + TROWS - 1) / TROWS;
    int ngemm = nrt * 4;
    int ntasks = ngemm + 9;
    int tid = threadIdx.x;
    int cp = tid % 150;
    int rg = tid / 150;                     // 0..1 -> rows rg*4..rg*4+3
    int jj = 2 * cp;
    int col0 = (jj < 150) ? jj : (jj + 2);  // g_T column of first of the pair

    for (int task = blockIdx.x; task < ntasks; task += gridDim.x) {
        if (task < ngemm) {
            int rt = task >> 2, ks = task & 3;
            int r0 = rt * TROWS, k0 = ks * 192;

            if (tid < TROWS) sRow[tid] = g_list[min(r0 + tid, cnt - 1)];
            __syncthreads();

            // stage A tile [k][8], consecutive stores, MLP-6 loads
            #pragma unroll
            for (int i = 0; i < 6; i++) {
                int idx = tid + i * 300;
                if (idx < 192 * TROWS) {
                    int k = idx >> 3, r = idx & 7;
                    sA[idx] = fmaxf(seq[(size_t)sRow[r] * HH + k0 + k], 0.f);
                }
            }
            stageW(sW, W1, k0);
            __syncthreads();

            ull acc[2][2];
            acc[0][0] = acc[0][1] = acc[1][0] = acc[1][1] = 0ull;

            #pragma unroll 1
            for (int c = 0; c < 8; c++) {
                if (c + 1 < 8)
                    stageW(sW + ((c + 1) & 1) * KCH * 304, W1, k0 + (c + 1) * KCH);
                const float* wb = sW + (c & 1) * KCH * 304;
                const float* ab = sA + c * KCH * TROWS + rg * 4;
                #pragma unroll
                for (int kk = 0; kk < KCH; kk++) {
                    ull wpair = *(const ull*)&wb[kk * 304 + jj];
                    float wx, wy;
                    unpack2(wpair, wx, wy);
                    ull b0 = pack2(wx), b1v = pack2(wy);
                    ull a0 = *(const ull*)&ab[kk * TROWS];
                    ull a1 = *(const ull*)&ab[kk * TROWS + 2];
                    acc[0][0] = ffma2(a0, b0,  acc[0][0]);
                    acc[0][1] = ffma2(a0, b1v, acc[0][1]);
                    acc[1][0] = ffma2(a1, b0,  acc[1][0]);
                    acc[1][1] = ffma2(a1, b1v, acc[1][1]);
                }
                __syncthreads();
            }

            int rbase = r0 + rg * 4;
            #pragma unroll
            for (int p = 0; p < 2; p++) {
                int rA = rbase + 2 * p;
                #pragma unroll
                for (int cc = 0; cc < 2; cc++) {
                    float lo, hi;
                    unpack2(acc[p][cc], lo, hi);
                    if (rA < cnt)
                        atomicAdd(&g_T[(size_t)rA * T_STRIDE + col0 + cc], lo);
                    if (rA + 1 < cnt)
                        atomicAdd(&g_T[(size_t)(rA + 1) * T_STRIDE + col0 + cc], hi);
                }
            }
            __syncthreads();
        } else {
            int w = task - ngemm;   // 0..8
            for (int t = tid; t < 150; t += 300) sA[t] = fmaxf(wt[w*150 + t], 0.f);
            __syncthreads();
            int g = tid / 150;      // 0..1
            int j = tid - g * 150;
            float acc = (g == 0) ? b1[j] : 0.f;
            int kst = g * 75;
            #pragma unroll 8
            for (int k = kst; k < kst + 75; k++)
                acc = fmaf(sA[k], W1[(size_t)(2*HH + k) * WE + j], acc);
            if (g == 1) sRed[j] = acc;
            __syncthreads();
            if (g == 0) g_WD[w * WD_STRIDE + j] = acc + sRed[j];
            __syncthreads();
        }
    }
}

// K5: unique rows -> h1 -> @W2+b2 (FFMA2) -> @W3+b3 -> g_ULOG. Work-stealing tiles.
#define UT 64
__global__ void __launch_bounds__(256, 1)
k_uniq(const float* __restrict__ W2, const float* __restrict__ b2,
       const float* __restrict__ W3, const float* __restrict__ b3)
{
    extern __shared__ float sm[];
    float* sW2 = sm;                     // [150][160]
    float* sU  = sm + 24000;             // union: h1T [152][64] / h2 [64][164]
    float* sW3 = sm + 34496;             // [150][12]
    float* sB2 = sm + 36296;             // [160]
    float* sB3 = sm + 36456;             // [12]
    unsigned* sInfo = (unsigned*)(sm + 36468);  // [64]
    int* sTile = (int*)(sm + 36468 + 64);
    int tid = threadIdx.x;

    for (int idx = tid; idx < 150*160; idx += 256) {
        int k = idx / 160, j = idx - k*160;
        sW2[idx] = (j < 150) ? W2[k*150 + j] : 0.f;
    }
    for (int idx = tid; idx < 150*12; idx += 256) {
        int k = idx / 12, l = idx - k*12;
        sW3[idx] = (l < 9) ? W3[k*9 + l] : 0.f;
    }
    if (tid < 160) sB2[tid] = (tid < 150) ? b2[tid] : 0.f;
    if (tid < 12)  sB3[tid] = (tid < 9)  ? b3[tid] : 0.f;

    int nu = g_ucount;
    int r0 = (tid & 15) * 4;     // 4 consecutive rows
    int c0 = (tid >> 4) * 10;    // 10 cols = 5 packed pairs

    for (;;) {
        if (tid == 0) *sTile = atomicAdd(&g_tile, 1);
        __syncthreads();
        int base = (*sTile) * UT;
        if (base >= nu) break;

        if (tid < UT)
            sInfo[tid] = (base + tid < nu) ? g_uinfo[base + tid] : 0u;
        __syncthreads();

        // gather h1, k-major [k][64], float4 over k
        for (int idx = tid; idx < 38*64; idx += 256) {
            int kq = idx >> 6, r = idx & 63;
            unsigned info = sInfo[r];
            int ss = info & 0x3FFF, se = (info >> 14) & 0x3FFF, w = info >> 28;
            float4 ts = *(const float4*)&g_T[(size_t)ss*T_STRIDE + kq*4];
            float4 te = *(const float4*)&g_T[(size_t)se*T_STRIDE + 152 + kq*4];
            float4 wd = *(const float4*)&g_WD[w*WD_STRIDE + kq*4];
            sU[(kq*4 + 0)*64 + r] = fmaxf(ts.x + te.x + wd.x, 0.f);
            sU[(kq*4 + 1)*64 + r] = fmaxf(ts.y + te.y + wd.y, 0.f);
            sU[(kq*4 + 2)*64 + r] = fmaxf(ts.z + te.z + wd.z, 0.f);
            sU[(kq*4 + 3)*64 + r] = fmaxf(ts.w + te.w + wd.w, 0.f);
        }
        __syncthreads();

        // h2 = h1 @ W2 + b2, packed column pairs (FFMA2)
        ull acc[4][5];
        {
            const ull* bp = (const ull*)&sB2[c0];
            #pragma unroll
            for (int p = 0; p < 5; p++) {
                ull bv = bp[p];
                #pragma unroll
                for (int ri = 0; ri < 4; ri++) acc[ri][p] = bv;
            }
        }
        #pragma unroll 2
        for (int k = 0; k < 150; k++) {
            float4 a = *(const float4*)&sU[k*64 + r0];
            ull ap[4] = {pack2(a.x), pack2(a.y), pack2(a.z), pack2(a.w)};
            const ull* bw = (const ull*)&sW2[k*160 + c0];
            ull bv[5] = {bw[0], bw[1], bw[2], bw[3], bw[4]};
            #pragma unroll
            for (int ri = 0; ri < 4; ri++)
                #pragma unroll
                for (int p = 0; p < 5; p++)
                    acc[ri][p] = ffma2(ap[ri], bv[p], acc[ri][p]);
        }
        __syncthreads();   // all h1 reads done before overwriting sU

        #pragma unroll
        for (int ri = 0; ri < 4; ri++)
            #pragma unroll
            for (int p = 0; p < 5; p++)
                *(ull*)&sU[(r0 + ri)*164 + c0 + 2*p] = acc[ri][p];
        __syncthreads();

        // logits = h2 @ W3 + b3
        for (int idx = tid; idx < UT*LL; idx += 256) {
            int r = idx / LL, l = idx - r*LL;
            float a = sB3[l];
            #pragma unroll 5
            for (int k = 0; k < 150; k++)
                a = fmaf(sU[r*164 + k], sW3[k*12 + l], a);
            if (base + r < nu)
                g_ULOG[(size_t)(base + r)*12 + l] = a;
        }
        __syncthreads();
    }
}

// K6: scatter logits per span + NLL loss + restore global state invariants
__global__ void k_scatter(const int* __restrict__ mask,
                          const int* __restrict__ label,
                          float* __restrict__ out)
{
    __shared__ float sL;
    if (threadIdx.x == 0) sL = 0.f;
    __syncthreads();
    int i = blockIdx.x * blockDim.x + threadIdx.x;
    float contrib = 0.f;
    if (i < NSPANS) {
        int key = g_key[i];
        int slot;
        if (key >= 0) { slot = g_uslot[key]; g_ckey[key] = 0; }
        else          { slot = g_spanslot[i]; }
        const float* Lr = &g_ULOG[(size_t)slot * 12];
        float4 p0 = *(const float4*)Lr;
        float4 p1 = *(const float4*)(Lr + 4);
        float l8 = Lr[8];
        float L[9] = {p0.x, p0.y, p0.z, p0.w, p1.x, p1.y, p1.z, p1.w, l8};
        float* o = out + (size_t)i * LL;
        #pragma unroll
        for (int l = 0; l < LL; l++) o[l] = L[l];
        if (mask[i] == 1) {
            float m = L[0];
            #pragma unroll
            for (int l = 1; l < LL; l++) m = fmaxf(m, L[l]);
            float ssum = 0.f;
            #pragma unroll
            for (int l = 0; l < LL; l++) ssum += expf(L[l] - m);
            int lb = clampi(label[i], 0, LL-1);
            contrib = (m + logf(ssum)) - L[lb];
        }
    }
    atomicAdd(&sL, contrib);
    __syncthreads();
    if (threadIdx.x == 0 && sL != 0.f)
        atomicAdd(&out[(size_t)NSPANS * LL], sL);
    if (blockIdx.x == 0 && threadIdx.x == 0) {
        g_count = 0; g_ucount = 0; g_tile = 0;
        #pragma unroll
        for (int w = 0; w < BB; w++) g_bcount[w] = 0;
    }
}

extern "C" void kernel_launch(void* const* d_in, const int* in_sizes, int n_in,
                              void* d_out, int out_size) {
    const float* seq = (const float*)d_in[0];
    const float* wt  = (const float*)d_in[1];
    const float* W1  = (const float*)d_in[2];
    const float* b1  = (const float*)d_in[3];
    const float* W2  = (const float*)d_in[4];
    const float* b2  = (const float*)d_in[5];
    const float* W3  = (const float*)d_in[6];
    const float* b3  = (const float*)d_in[7];
    const int* spans = (const int*)d_in[8];
    const int* smask = (const int*)d_in[9];
    const int* slab  = (const int*)d_in[10];
    float* out = (float*)d_out;

    static const size_t SMEM_UNIQ = (size_t)(36468 + 64 + 4) * 4;
    static const size_t SMEM_TG   = (size_t)(2*KCH*304 + 192*TROWS + 8 + 160 + 8) * 4;
    cudaFuncSetAttribute(k_uniq, cudaFuncAttributeMaxDynamicSharedMemorySize, (int)SMEM_UNIQ);
    cudaFuncSetAttribute(k_TgemmWD, cudaFuncAttributeMaxDynamicSharedMemorySize, (int)SMEM_TG);

    k_mark<<<NSPANS/256, 256>>>(spans, out + (size_t)NSPANS * LL);
    k_compact<<<NPOS/256, 256>>>();
    k_claim<<<544, 256>>>(spans);
    k_TgemmWD<<<160, 300, SMEM_TG>>>(seq, W1, wt, b1);
    k_uniq<<<148, 256, SMEM_UNIQ>>>(W2, b2, W3, b3);
    k_scatter<<<NSPANS/256, 256>>>(smask, slab, out);
}